// round 9
// baseline (speedup 1.0000x reference)
#include <cuda_runtime.h>
#include <stdint.h>

// Static problem shape: B=64, C=16, H=128, W=128
#define DIM  16384u                 // H*W floats (scale table)
#define NTOT 16777216u              // B*C*H*W elements
#define NVEC (NTOT / 4u)            // float4 chunks

__device__ __align__(16) float g_scale[DIM];

__global__ void exp_betas_kernel(const float* __restrict__ betas) {
    unsigned i = blockIdx.x * blockDim.x + threadIdx.x;
    if (i < DIM) g_scale[i] = __expf(betas[i]);
}

// R6 structure, inverted cache policy:
//   x loads  : __ldcs (evict-first) -> x streams, does NOT pollute L2
//   out store: plain STG (write-allocate, evict-normal) -> output stays
//              dirty-resident in L2 across graph replays => write hits,
//              no DRAM write drain in steady state.
__global__ void __launch_bounds__(256) diag_scale_real16(
        const float4* __restrict__ xr4, float4* __restrict__ out4) {
    const unsigned base = blockIdx.x * 1024u + threadIdx.x;

    float4 r[4], s[4];
#pragma unroll
    for (int k = 0; k < 4; k++) {
        const unsigned idx = base + k * 256u;
        r[k] = __ldcs(&xr4[idx]);                       // streaming read
        s[k] = *reinterpret_cast<const float4*>(
                   &g_scale[(idx * 4u) & (DIM - 1u)]);  // tiny, stays hot
    }
#pragma unroll
    for (int k = 0; k < 4; k++) {
        const unsigned idx = base + k * 256u;
        float4 o;
        o.x = r[k].x * s[k].x;
        o.y = r[k].y * s[k].y;
        o.z = r[k].z * s[k].z;
        o.w = r[k].w * s[k].w;
        out4[idx] = o;                                  // L2 write-allocate
    }
}

// ------- fallback paths (kept from passing versions) -------
__global__ void diag_scale_real1(const float* __restrict__ xr,
                                 float* __restrict__ out) {
    const unsigned i = blockIdx.x * blockDim.x + threadIdx.x;
    if (i < NTOT) out[i] = xr[i] * g_scale[i & (DIM - 1u)];
}
__global__ void diag_scale_cplx4(const float4* __restrict__ xr4,
                                 const float4* __restrict__ xi4,
                                 float4* __restrict__ out4) {
    const unsigned t = blockIdx.x * blockDim.x + threadIdx.x;
    const unsigned pos = (t * 4u) & (DIM - 1u);
    const float4 s  = *reinterpret_cast<const float4*>(&g_scale[pos]);
    const float4 r  = xr4[t];
    const float4 im = xi4[t];
    float4 o0, o1;
    o0.x = r.x * s.x;  o0.y = im.x * s.x;
    o0.z = r.y * s.y;  o0.w = im.y * s.y;
    o1.x = r.z * s.z;  o1.y = im.z * s.z;
    o1.z = r.w * s.w;  o1.w = im.w * s.w;
    out4[2u * t]      = o0;
    out4[2u * t + 1u] = o1;
}
__global__ void diag_scale_cplx1(const float* __restrict__ xr,
                                 const float* __restrict__ xi,
                                 float* __restrict__ out) {
    const unsigned i = blockIdx.x * blockDim.x + threadIdx.x;
    if (i < NTOT) {
        const float s = g_scale[i & (DIM - 1u)];
        out[2u * i]      = xr[i] * s;
        out[2u * i + 1u] = xi[i] * s;
    }
}

extern "C" void kernel_launch(void* const* d_in, const int* in_sizes, int n_in,
                              void* d_out, int out_size) {
    // Relative-size input identification: smallest = betas; others in order.
    int min_idx = 0;
    for (int i = 1; i < n_in; i++)
        if (in_sizes[i] < in_sizes[min_idx]) min_idx = i;

    const float* betas  = (const float*)d_in[min_idx];
    const float* x_real = nullptr;
    const float* x_imag = nullptr;
    for (int i = 0; i < n_in; i++) {
        if (i == min_idx) continue;
        if (!x_real)      x_real = (const float*)d_in[i];
        else if (!x_imag) { x_imag = (const float*)d_in[i]; break; }
    }
    if (!x_real || !betas || !d_out) return;
    if (!x_imag) x_imag = x_real;

    exp_betas_kernel<<<(DIM + 255u) / 256u, 256>>>(betas);

    const bool aligned16 =
        (((uintptr_t)x_real | (uintptr_t)x_imag | (uintptr_t)d_out) & 15u) == 0u;
    const unsigned budget = (unsigned)out_size;

    if (budget >= 2u * NTOT) {
        if (aligned16)
            diag_scale_cplx4<<<NVEC / 256u, 256>>>(
                (const float4*)x_real, (const float4*)x_imag, (float4*)d_out);
        else
            diag_scale_cplx1<<<NTOT / 256u, 256>>>(x_real, x_imag, (float*)d_out);
    } else {
        if (aligned16)
            diag_scale_real16<<<NVEC / 1024u, 256>>>(
                (const float4*)x_real, (float4*)d_out);
        else
            diag_scale_real1<<<NTOT / 256u, 256>>>(x_real, (float*)d_out);
    }
}

// round 10
// speedup vs baseline: 1.0976x; 1.0976x over previous
#include <cuda_runtime.h>
#include <stdint.h>

// Static problem shape: B=64, C=16, H=128, W=128
#define DIM  16384u                 // H*W floats (betas)
#define NTOT 16777216u              // B*C*H*W elements
#define NVEC (NTOT / 4u)            // float4 chunks

__device__ __align__(16) float g_scale[DIM];

__global__ void exp_betas_kernel(const float* __restrict__ betas) {
    unsigned i = blockIdx.x * blockDim.x + threadIdx.x;
    if (i < DIM) g_scale[i] = __expf(betas[i]);
}

// FUSED single-kernel path: 4 float4s (16 floats) per thread.
// betas loaded directly (64 KiB, L1/L2-hot after first wave) and exp'd
// inline — 16 MUFU-EX2 per thread hides entirely under memory stalls
// (issue was 10.5% busy). Removes the prologue kernel + its graph node.
__global__ void __launch_bounds__(256) diag_scale_fused(
        const float4* __restrict__ xr4,
        const float4* __restrict__ betas4,   // DIM/4 float4s
        float4* __restrict__ out4) {
    const unsigned base = blockIdx.x * 1024u + threadIdx.x;

    float4 r[4], b[4];
#pragma unroll
    for (int k = 0; k < 4; k++) {
        const unsigned idx = base + k * 256u;
        r[k] = __ldcs(&xr4[idx]);                    // streaming read
        b[k] = betas4[idx & (DIM / 4u - 1u)];        // hot after wave 1
    }
#pragma unroll
    for (int k = 0; k < 4; k++) {
        const unsigned idx = base + k * 256u;
        float4 o;
        o.x = r[k].x * __expf(b[k].x);
        o.y = r[k].y * __expf(b[k].y);
        o.z = r[k].z * __expf(b[k].z);
        o.w = r[k].w * __expf(b[k].w);
        out4[idx] = o;
    }
}

// ------- fallback paths (two-kernel, from passing versions) -------
__global__ void diag_scale_real1(const float* __restrict__ xr,
                                 float* __restrict__ out) {
    const unsigned i = blockIdx.x * blockDim.x + threadIdx.x;
    if (i < NTOT) out[i] = xr[i] * g_scale[i & (DIM - 1u)];
}
__global__ void diag_scale_cplx4(const float4* __restrict__ xr4,
                                 const float4* __restrict__ xi4,
                                 float4* __restrict__ out4) {
    const unsigned t = blockIdx.x * blockDim.x + threadIdx.x;
    const unsigned pos = (t * 4u) & (DIM - 1u);
    const float4 s  = *reinterpret_cast<const float4*>(&g_scale[pos]);
    const float4 r  = xr4[t];
    const float4 im = xi4[t];
    float4 o0, o1;
    o0.x = r.x * s.x;  o0.y = im.x * s.x;
    o0.z = r.y * s.y;  o0.w = im.y * s.y;
    o1.x = r.z * s.z;  o1.y = im.z * s.z;
    o1.z = r.w * s.w;  o1.w = im.w * s.w;
    out4[2u * t]      = o0;
    out4[2u * t + 1u] = o1;
}
__global__ void diag_scale_cplx1(const float* __restrict__ xr,
                                 const float* __restrict__ xi,
                                 float* __restrict__ out) {
    const unsigned i = blockIdx.x * blockDim.x + threadIdx.x;
    if (i < NTOT) {
        const float s = g_scale[i & (DIM - 1u)];
        out[2u * i]      = xr[i] * s;
        out[2u * i + 1u] = xi[i] * s;
    }
}

extern "C" void kernel_launch(void* const* d_in, const int* in_sizes, int n_in,
                              void* d_out, int out_size) {
    // Relative-size input identification: smallest = betas; others in order.
    int min_idx = 0;
    for (int i = 1; i < n_in; i++)
        if (in_sizes[i] < in_sizes[min_idx]) min_idx = i;

    const float* betas  = (const float*)d_in[min_idx];
    const float* x_real = nullptr;
    const float* x_imag = nullptr;
    for (int i = 0; i < n_in; i++) {
        if (i == min_idx) continue;
        if (!x_real)      x_real = (const float*)d_in[i];
        else if (!x_imag) { x_imag = (const float*)d_in[i]; break; }
    }
    if (!x_real || !betas || !d_out) return;
    if (!x_imag) x_imag = x_real;

    const bool aligned16 =
        (((uintptr_t)x_real | (uintptr_t)x_imag | (uintptr_t)d_out
          | (uintptr_t)betas) & 15u) == 0u;
    const unsigned budget = (unsigned)out_size;

    if (budget >= 2u * NTOT) {
        exp_betas_kernel<<<(DIM + 255u) / 256u, 256>>>(betas);
        if (aligned16)
            diag_scale_cplx4<<<NVEC / 256u, 256>>>(
                (const float4*)x_real, (const float4*)x_imag, (float4*)d_out);
        else
            diag_scale_cplx1<<<NTOT / 256u, 256>>>(x_real, x_imag, (float*)d_out);
    } else {
        if (aligned16) {
            // single fused kernel — no prologue node
            diag_scale_fused<<<NVEC / 1024u, 256>>>(
                (const float4*)x_real, (const float4*)betas, (float4*)d_out);
        } else {
            exp_betas_kernel<<<(DIM + 255u) / 256u, 256>>>(betas);
            diag_scale_real1<<<NTOT / 256u, 256>>>(x_real, (float*)d_out);
        }
    }
}